// round 9
// baseline (speedup 1.0000x reference)
#include <cuda_runtime.h>
#include <cstdint>
#include <cstddef>

// router_20091857011524: fused 4-way router (GB300 sm_103a) — R9
// R8 minus the cp.async ring: x loads go LDG.128 -> registers directly
// (depth-1 prefetch), which in the j-lane layout is perfectly coalesced
// (4 token rows x 128B per instruction). smem holds ONLY the permuted W
// planes (64KB) -> 3 blocks/SM, 24 warps. W reads stay conflict-free
// 128B-broadcast LDS. Logits reduced via shfl_xor; per-lane epilogue;
// phase C L2-hot (traffic already measured at the 320MB ideal in R8).

#define THREADS 256
#define TPB_TOK 32          // 8 warps x 4 tokens
#define NG 16               // 512 dims / 32 per group

#define SMEM_FLOATS (8 * 512 * 4)     // 8 o-planes x 512 float4
#define SMEM_BYTES  (SMEM_FLOATS * 4) // 65536

__global__ __launch_bounds__(THREADS)
void router_kernel(const float* __restrict__ m0, const float* __restrict__ m1,
                   const float* __restrict__ m2, const float* __restrict__ m3,
                   const float* __restrict__ Wt, const float* __restrict__ bt,
                   const float* __restrict__ Ws, const float* __restrict__ bs,
                   const float* __restrict__ alpha, float* __restrict__ out)
{
    extern __shared__ float smem[];
    float4* wsm = reinterpret_cast<float4*>(smem);

    const int tid  = threadIdx.x;
    const int lane = tid & 31;
    const int wrp  = tid >> 5;
    const int t    = lane >> 3;    // token within warp (0..3)
    const int j    = lane & 7;     // dim slot (0..7)

    // ---- stage W once: wsm[o*512 + g*32 + jj*8 + js], where for dim d:
    // g = d>>5, js = (d>>2)&7, jj = d&3.  Lane j owns dims g*32 + j*4 + jj.
    {
        const float4* wt4 = reinterpret_cast<const float4*>(Wt);
        const float4* ws4 = reinterpret_cast<const float4*>(Ws);
        #pragma unroll
        for (int rep = 0; rep < 16; rep++) {
            const int i  = tid + rep * THREADS;   // 0..4095
            const int o  = i >> 9;
            const int dd = i & 511;
            float4 v = (o < 4) ? __ldg(wt4 + o * 512 + dd)
                               : __ldg(ws4 + (o - 4) * 512 + dd);
            const int g = dd >> 5, jj = dd & 3, js = (dd >> 2) & 7;
            wsm[o * 512 + g * 32 + jj * 8 + js] = v;
        }
    }
    __syncthreads();   // the ONLY block barrier

    const int tok = blockIdx.x * TPB_TOK + wrp * 4 + t;
    const size_t row = (size_t)tok * 512;
    const float4* q0 = reinterpret_cast<const float4*>(m0 + row);
    const float4* q1 = reinterpret_cast<const float4*>(m1 + row);
    const float4* q2 = reinterpret_cast<const float4*>(m2 + row);
    const float4* q3 = reinterpret_cast<const float4*>(m3 + row);

    float acc[8];
    #pragma unroll
    for (int o = 0; o < 8; o++) acc[o] = 0.f;

    // ---- main loop: LDG.128 direct to regs, depth-1 prefetch
    float4 c0 = __ldg(q0 + j);
    float4 c1 = __ldg(q1 + j);
    float4 c2 = __ldg(q2 + j);
    float4 c3 = __ldg(q3 + j);

    #pragma unroll 4
    for (int g = 0; g < NG; g++) {
        float4 n0, n1, n2, n3;
        if (g + 1 < NG) {
            const int idx = (g + 1) * 8 + j;
            n0 = __ldg(q0 + idx);
            n1 = __ldg(q1 + idx);
            n2 = __ldg(q2 + idx);
            n3 = __ldg(q3 + idx);
        }
        const float* f0 = reinterpret_cast<const float*>(&c0);
        const float* f1 = reinterpret_cast<const float*>(&c1);
        const float* f2 = reinterpret_cast<const float*>(&c2);
        const float* f3 = reinterpret_cast<const float*>(&c3);
        #pragma unroll
        for (int jj = 0; jj < 4; jj++) {
            #pragma unroll
            for (int o = 0; o < 8; o++) {
                float4 w = wsm[o * 512 + g * 32 + jj * 8 + j];  // 128B broadcast LDS
                acc[o] += f0[jj] * w.x + f1[jj] * w.y + f2[jj] * w.z + f3[jj] * w.w;
            }
        }
        if (g + 1 < NG) { c0 = n0; c1 = n1; c2 = n2; c3 = n3; }
    }

    // ---- reduce over the 8 j-lanes (butterfly: all lanes get full sums)
    #pragma unroll
    for (int m = 1; m < 8; m <<= 1) {
        #pragma unroll
        for (int o = 0; o < 8; o++)
            acc[o] += __shfl_xor_sync(0xffffffffu, acc[o], m);
    }

    // ---- per-token epilogue (redundant across the 8 j-lanes)
    float w[4];
    {
        float lt[4], ls[4];
        #pragma unroll
        for (int kp = 0; kp < 4; kp++) {
            lt[kp] = acc[kp]     + __ldg(bt + kp);
            ls[kp] = acc[4 + kp] + __ldg(bs + kp);
        }
        // top-2 (first-index tie semantics like jax top_k)
        int i0 = 0; float v0 = lt[0];
        #pragma unroll
        for (int k = 1; k < 4; k++) if (lt[k] > v0) { v0 = lt[k]; i0 = k; }
        int i1 = -1; float v1 = -3.0e38f;
        #pragma unroll
        for (int k = 0; k < 4; k++) if (k != i0 && lt[k] > v1) { v1 = lt[k]; i1 = k; }
        const float e  = __expf(v1 - v0);
        const float s2 = 1.0f / (1.0f + e);
        const float p0 = s2;
        const float p1 = e * s2;
        const float mx = fmaxf(fmaxf(ls[0], ls[1]), fmaxf(ls[2], ls[3]));
        float es[4];
        #pragma unroll
        for (int k = 0; k < 4; k++) es[k] = __expf(ls[k] - mx);
        const float inv = 1.0f / (es[0] + es[1] + es[2] + es[3]);
        const float a = 1.0f / (1.0f + __expf(-__ldg(alpha)));
        #pragma unroll
        for (int k = 0; k < 4; k++) {
            const float hard = (k == i0) ? p0 : ((k == i1) ? p1 : 0.0f);
            w[k] = a * hard + (1.0f - a) * (es[k] * inv);
        }
    }

    // ---- phase C: weighted sum for this lane's token; L2-hot re-read
    {
        float4* po = reinterpret_cast<float4*>(out + row);
        #pragma unroll 4
        for (int r = 0; r < 16; r++) {
            const int f = j + 8 * r;    // 8 lanes -> 128B contiguous per row
            float4 va = __ldcs(q0 + f);
            float4 vb = __ldcs(q1 + f);
            float4 vc = __ldcs(q2 + f);
            float4 vd = __ldcs(q3 + f);
            float4 o4;
            o4.x = w[0] * va.x + w[1] * vb.x + w[2] * vc.x + w[3] * vd.x;
            o4.y = w[0] * va.y + w[1] * vb.y + w[2] * vc.y + w[3] * vd.y;
            o4.z = w[0] * va.z + w[1] * vb.z + w[2] * vc.z + w[3] * vd.z;
            o4.w = w[0] * va.w + w[1] * vb.w + w[2] * vc.w + w[3] * vd.w;
            po[f] = o4;
        }
    }
}

extern "C" void kernel_launch(void* const* d_in, const int* in_sizes, int n_in,
                              void* d_out, int out_size)
{
    const float* m0    = (const float*)d_in[0];
    const float* m1    = (const float*)d_in[1];
    const float* m2    = (const float*)d_in[2];
    const float* m3    = (const float*)d_in[3];
    const float* W_top = (const float*)d_in[4];
    const float* b_top = (const float*)d_in[5];
    const float* W_sft = (const float*)d_in[6];
    const float* b_sft = (const float*)d_in[7];
    const float* alpha = (const float*)d_in[8];
    float* out = (float*)d_out;

    const int ntok = in_sizes[0] / 512;       // 32768
    const int grid = ntok / TPB_TOK;          // 1024

    cudaFuncSetAttribute(router_kernel,
                         cudaFuncAttributeMaxDynamicSharedMemorySize, SMEM_BYTES);
    router_kernel<<<grid, THREADS, SMEM_BYTES>>>(m0, m1, m2, m3,
                                                 W_top, b_top, W_sft, b_sft,
                                                 alpha, out);
}